// round 11
// baseline (speedup 1.0000x reference)
#include <cuda_runtime.h>
#include <cuda_fp16.h>
#include <math.h>
#include <stdint.h>

// ---------------- problem constants ----------------
#define E   8
#define D   1024
#define H   4096
#define TK  2
#define T   4096      // B*S

#define BM  128
#define BN  128
#define BK  64
#define PIPE 3
#define NTHREADS 128   // 4 warps, 2x2, warp tile 64x64

#define CAP    4096               // fixed per-expert row capacity
#define RTILES (E * CAP / BM)     // 256 row tiles
#define TPE    (CAP / BM)         // 32 tiles per expert

#define ASTR 72     // halves: 64 + 8 pad
#define BSTR 136    // halves: 128 + 8 pad
#define ASZ (BM * ASTR * 2)
#define BSZ (BK * BSTR * 2)
#define SMEM_DYN (PIPE*ASZ + PIPE*BSZ)   // 107520 B

#define NROUTER_BLOCKS 512
#define NW4 (E * D * H / 4)    // float4 per weight tensor = 8388608
#define CONV_PER_CTA 1024      // float4 of w2 per GEMM1 CTA (8192 CTAs total)

// ---------------- scratch ----------------
// g_fill zero-initialized at load; combine re-zeroes it after every run.
__device__ int    g_fill[E];
__device__ int    g_tok[E * CAP];
__device__ int    g_slot[T * TK];
__device__ int    g_texp[T * TK];
__device__ float  g_tprob[T * TK];
__device__ __half g_xh[(size_t)T * D];
__device__ __half g_w1h[(size_t)E * D * H];
__device__ __half g_w2h[(size_t)E * H * D];
__device__ __half g_h1[(size_t)E * CAP * H];
__device__ float  g_y [(size_t)E * CAP * D];

// ---------------- helpers ----------------
static __device__ __forceinline__ uint32_t smem_u32(const void* p) {
    uint32_t a;
    asm("{ .reg .u64 t; cvta.to.shared.u64 t, %1; cvt.u32.u64 %0, t; }"
        : "=r"(a) : "l"(p));
    return a;
}
static __device__ __forceinline__ void cp_async16(uint32_t saddr, const void* gaddr) {
    asm volatile("cp.async.cg.shared.global [%0], [%1], 16;"
                 :: "r"(saddr), "l"(gaddr));
}
#define LDSM_X4(r0,r1,r2,r3,addr) \
    asm volatile("ldmatrix.sync.aligned.m8n8.x4.shared.b16 {%0,%1,%2,%3}, [%4];" \
                 : "=r"(r0), "=r"(r1), "=r"(r2), "=r"(r3) : "r"(addr))
#define LDSM_X4T(r0,r1,r2,r3,addr) \
    asm volatile("ldmatrix.sync.aligned.m8n8.x4.trans.shared.b16 {%0,%1,%2,%3}, [%4];" \
                 : "=r"(r0), "=r"(r1), "=r"(r2), "=r"(r3) : "r"(addr))

static __device__ __forceinline__ void mma_f16(float* d,
                                               const uint32_t* a,
                                               const uint32_t* b) {
    asm volatile(
        "mma.sync.aligned.m16n8k16.row.col.f32.f16.f16.f32 "
        "{%0,%1,%2,%3}, {%4,%5,%6,%7}, {%8,%9}, {%0,%1,%2,%3};"
        : "+f"(d[0]), "+f"(d[1]), "+f"(d[2]), "+f"(d[3])
        : "r"(a[0]), "r"(a[1]), "r"(a[2]), "r"(a[3]), "r"(b[0]), "r"(b[1]));
}
static __device__ __forceinline__ uint2 f4_to_h4(float4 v) {
    __half2 a = __float22half2_rn(make_float2(v.x, v.y));
    __half2 b = __float22half2_rn(make_float2(v.z, v.w));
    return make_uint2(*(uint32_t*)&a, *(uint32_t*)&b);
}

// ---------------- fused router (+scatter) + w1 conversion ----------------
__global__ void __launch_bounds__(256)
fused_prep_kernel(const float* __restrict__ x,
                  const float* __restrict__ rw,
                  const float* __restrict__ rb,
                  const float4* __restrict__ w1s, uint2* __restrict__ w1d,
                  float* __restrict__ out_logits) {
    if (blockIdx.x >= NROUTER_BLOCKS) {
        int i = (blockIdx.x - NROUTER_BLOCKS) * blockDim.x + threadIdx.x;
        if (i < NW4) w1d[i] = f4_to_h4(w1s[i]);
        return;
    }

    int warp = threadIdx.x >> 5;
    int lane = threadIdx.x & 31;
    int t = blockIdx.x * 8 + warp;
    if (t >= T) return;

    const float* xt = x + (size_t)t * D;
    __half* xh = g_xh + (size_t)t * D;
    float acc[E];
#pragma unroll
    for (int e = 0; e < E; e++) acc[e] = 0.f;
#pragma unroll 4
    for (int i = 0; i < D / 64; i++) {
        int k = i * 64 + lane * 2;
        float2 xv = *(const float2*)(xt + k);
        *(__half2*)(xh + k) = __float22half2_rn(xv);
        const float* r0 = rw + (size_t)k * E;
#pragma unroll
        for (int e = 0; e < E; e++) acc[e] += xv.x * r0[e] + xv.y * r0[E + e];
    }
#pragma unroll
    for (int off = 16; off > 0; off >>= 1)
#pragma unroll
        for (int e = 0; e < E; e++)
            acc[e] += __shfl_down_sync(0xffffffffu, acc[e], off);

    if (lane == 0) {
        float l[E];
#pragma unroll
        for (int e = 0; e < E; e++) {
            l[e] = acc[e] + rb[e];
            out_logits[(size_t)t * E + e] = l[e];
        }
        int i0 = 0;
#pragma unroll
        for (int e = 1; e < E; e++) if (l[e] > l[i0]) i0 = e;
        int i1 = -1;
#pragma unroll
        for (int e = 0; e < E; e++) {
            if (e == i0) continue;
            if (i1 < 0 || l[e] > l[i1]) i1 = e;
        }
        float m = l[i0], s = 0.f;
#pragma unroll
        for (int e = 0; e < E; e++) s += expf(l[e] - m);
        float p0 = expf(l[i0] - m) / s;
        float p1 = expf(l[i1] - m) / s;
        float inv = 1.f / (p0 + p1);
        p0 *= inv; p1 *= inv;

        g_texp[t * 2 + 0] = i0;  g_texp[t * 2 + 1] = i1;
        g_tprob[t * 2 + 0] = p0; g_tprob[t * 2 + 1] = p1;

        // direct scatter into fixed-capacity regions
        int pos0 = atomicAdd(&g_fill[i0], 1);
        int pos1 = atomicAdd(&g_fill[i1], 1);
        int s0 = i0 * CAP + pos0, s1 = i1 * CAP + pos1;
        g_tok[s0] = t; g_tok[s1] = t;
        g_slot[t * 2 + 0] = s0; g_slot[t * 2 + 1] = s1;
    }
}

// ---------------- fp16 mma.sync grouped GEMM (frozen R10 mainloop) ----------------
// Fixed-capacity grid: y in [0, RTILES); expert = y/TPE; tile row = (y%TPE)*BM.
// Tiles beyond the expert's fill count early-exit (after their conv slice).
template<int KTOT, int NLD, bool GELU, bool GATHER, bool CONV>
__global__ void __launch_bounds__(NTHREADS, 2)
moe_gemm(const float* __restrict__ bias,
         const float4* __restrict__ cvs, uint2* __restrict__ cvd) {
    const __half* Aall = GATHER ? g_xh : g_h1;
    const __half* Ball = GELU ? g_w1h : g_w2h;

    int tid = threadIdx.x;
    int cbase;
    if (CONV) cbase = (blockIdx.y * gridDim.x + blockIdx.x) * CONV_PER_CTA;

    int e = blockIdx.y / TPE;
    int rloc = (blockIdx.y % TPE) * BM;
    int count = g_fill[e];
    if (rloc >= count) {
        if (CONV) {
#pragma unroll 4
            for (int j = 0; j < CONV_PER_CTA / NTHREADS; j++) {
                int k = cbase + j * NTHREADS + tid;
                cvd[k] = f4_to_h4(cvs[k]);
            }
        }
        return;
    }
    int row0 = e * CAP + rloc;             // global slot base for this tile
    int lim = count - rloc;                // valid rows in tile (>=1)
    int col0 = blockIdx.x * BN;
    const __half* Bexp = Ball + (size_t)e * KTOT * NLD + col0;

    extern __shared__ __align__(16) char dsm[];
    __shared__ int s_tok[BM];

    int wid = tid >> 5, lane = tid & 31;
    int wm = wid & 1, wn = wid >> 1;
    int g = lane >> 2, tg = lane & 3;
    int l15 = lane & 15, l16 = (lane >> 4) * 8;

    if (GATHER) s_tok[tid] = g_tok[row0 + (tid < lim ? tid : 0)];
    __syncthreads();

    uint32_t sAb = smem_u32(dsm);
    uint32_t sBb = sAb + PIPE * ASZ;

    const __half* a_gptr[8];
#pragma unroll
    for (int i = 0; i < 8; i++) {
        int idx = tid + i * NTHREADS;
        int r = idx >> 3, c = idx & 7;
        int rowid;
        if (GATHER) rowid = s_tok[r];
        else        rowid = row0 + r;      // pad rows hold well-defined data
        a_gptr[i] = Aall + (size_t)rowid * KTOT + c * 8;
    }
    const __half* b_gptr[8];
#pragma unroll
    for (int i = 0; i < 8; i++) {
        int idx = tid + i * NTHREADS;
        b_gptr[i] = Bexp + (size_t)(idx >> 4) * NLD + (idx & 15) * 8;
    }

    auto issue_copy = [&](int chunk, int buf) {
        uint32_t sa = sAb + buf * ASZ;
        uint32_t sb = sBb + buf * BSZ;
        int k0 = chunk * BK;
#pragma unroll
        for (int i = 0; i < 8; i++) {
            int idx = tid + i * NTHREADS;
            int r = idx >> 3, c = idx & 7;
            cp_async16(sa + (uint32_t)(r * ASTR + c * 8) * 2, a_gptr[i] + k0);
        }
#pragma unroll
        for (int i = 0; i < 8; i++) {
            int idx = tid + i * NTHREADS;
            int r = idx >> 4, c = idx & 15;
            cp_async16(sb + (uint32_t)(r * BSTR + c * 8) * 2,
                       b_gptr[i] + (size_t)k0 * NLD);
        }
        asm volatile("cp.async.commit_group;" ::: "memory");
    };

    float acc[4][8][4];
#pragma unroll
    for (int mf = 0; mf < 4; mf++)
#pragma unroll
        for (int nf = 0; nf < 8; nf++)
#pragma unroll
            for (int r = 0; r < 4; r++) acc[mf][nf][r] = 0.f;

    const int NC = KTOT / BK;   // 16 (gemm1) / 64 (gemm2)
    const int NCONV = CONV_PER_CTA / (2 * NTHREADS);   // 4 conv chunks

    float4 cv0, cv1;
    if (CONV) {
        cv0 = cvs[cbase + tid];
        cv1 = cvs[cbase + NTHREADS + tid];
    }

    issue_copy(0, 0);
    issue_copy(1, 1);

    int buf = 0;
    for (int i = 0; i < NC; i++) {
        if (i + 1 < NC) asm volatile("cp.async.wait_group 1;" ::: "memory");
        else            asm volatile("cp.async.wait_group 0;" ::: "memory");
        __syncthreads();

        if (CONV && i < NCONV) {
            int k0 = cbase + i * 2 * NTHREADS + tid;
            int k1 = k0 + NTHREADS;
            cvd[k0] = f4_to_h4(cv0);
            cvd[k1] = f4_to_h4(cv1);
            if (i + 1 < NCONV) {
                cv0 = cvs[k0 + 2 * NTHREADS];
                cv1 = cvs[k1 + 2 * NTHREADS];
            }
        }

        if (i + 2 < NC) {
            int nb = buf + 2; if (nb >= PIPE) nb -= PIPE;
            issue_copy(i + 2, nb);
        }

        uint32_t sa = sAb + buf * ASZ;
        uint32_t sb = sBb + buf * BSZ;

#pragma unroll
        for (int kk = 0; kk < BK / 16; kk++) {
            uint32_t af[4][4];
#pragma unroll
            for (int mf = 0; mf < 4; mf++) {
                uint32_t addr = sa + (uint32_t)((wm * 64 + mf * 16 + l15) * ASTR
                                                + kk * 16 + l16) * 2;
                LDSM_X4(af[mf][0], af[mf][1], af[mf][2], af[mf][3], addr);
            }
            uint32_t bf[8][2];
#pragma unroll
            for (int pf = 0; pf < 4; pf++) {
                uint32_t addr = sb + (uint32_t)((kk * 16 + l15) * BSTR
                                                + wn * 64 + pf * 16 + l16) * 2;
                uint32_t r0, r1, r2, r3;
                LDSM_X4T(r0, r1, r2, r3, addr);
                bf[pf * 2][0] = r0;     bf[pf * 2][1] = r1;
                bf[pf * 2 + 1][0] = r2; bf[pf * 2 + 1][1] = r3;
            }
#pragma unroll
            for (int mf = 0; mf < 4; mf++)
#pragma unroll
                for (int nf = 0; nf < 8; nf++)
                    mma_f16(acc[mf][nf], af[mf], bf[nf]);
        }
        buf++; if (buf >= PIPE) buf -= PIPE;
    }

    // epilogue
    const float* be = bias + (size_t)e * NLD + col0 + wn * 64;
#pragma unroll
    for (int mf = 0; mf < 4; mf++) {
        int r0 = row0 + wm * 64 + mf * 16 + g;
#pragma unroll
        for (int nf = 0; nf < 8; nf++) {
            int cl = nf * 8 + tg * 2;
            float b0 = be[cl], b1 = be[cl + 1];
            float v0 = acc[mf][nf][0] + b0;
            float v1 = acc[mf][nf][1] + b1;
            float v2 = acc[mf][nf][2] + b0;
            float v3 = acc[mf][nf][3] + b1;
            int c = col0 + wn * 64 + cl;
            if (GELU) {
                const float kk = 0.70710678118654752440f;
                v0 = 0.5f * v0 * (1.f + erff(v0 * kk));
                v1 = 0.5f * v1 * (1.f + erff(v1 * kk));
                v2 = 0.5f * v2 * (1.f + erff(v2 * kk));
                v3 = 0.5f * v3 * (1.f + erff(v3 * kk));
                __half2 h01 = __float22half2_rn(make_float2(v0, v1));
                __half2 h23 = __float22half2_rn(make_float2(v2, v3));
                *(__half2*)(g_h1 + (size_t)r0 * NLD + c)       = h01;
                *(__half2*)(g_h1 + (size_t)(r0 + 8) * NLD + c) = h23;
            } else {
                *(float2*)(g_y + (size_t)r0 * NLD + c)       = make_float2(v0, v1);
                *(float2*)(g_y + (size_t)(r0 + 8) * NLD + c) = make_float2(v2, v3);
            }
        }
    }
}

// ---------------- combine (+fill re-zero for next replay) ----------------
__global__ void __launch_bounds__(256)
combine_kernel(const float* __restrict__ x,
               const float* __restrict__ gamma,
               const float* __restrict__ beta,
               float* __restrict__ out) {
    int t = blockIdx.x;
    int tid = threadIdx.x;

    if (blockIdx.x == 0 && tid < E) g_fill[tid] = 0;

    int s0 = g_slot[t * 2 + 0], s1 = g_slot[t * 2 + 1];
    int e0 = g_texp[t * 2 + 0], e1 = g_texp[t * 2 + 1];
    float p0 = g_tprob[t * 2 + 0], p1 = g_tprob[t * 2 + 1];

    const float* y0 = g_y + (size_t)s0 * D;
    const float* y1 = g_y + (size_t)s1 * D;
    const float* xt = x + (size_t)t * D;

    float v0[4], v1[4];
    float sum0 = 0.f, sq0 = 0.f, sum1 = 0.f, sq1 = 0.f;
#pragma unroll
    for (int i = 0; i < 4; i++) {
        int d = tid + i * 256;
        float xv = xt[d];
        v0[i] = y0[d] + xv;
        v1[i] = y1[d] + xv;
        sum0 += v0[i]; sq0 += v0[i] * v0[i];
        sum1 += v1[i]; sq1 += v1[i] * v1[i];
    }

    __shared__ float sh[4][8];
    int lane = tid & 31, wid = tid >> 5;
#pragma unroll
    for (int off = 16; off > 0; off >>= 1) {
        sum0 += __shfl_down_sync(0xffffffffu, sum0, off);
        sq0  += __shfl_down_sync(0xffffffffu, sq0,  off);
        sum1 += __shfl_down_sync(0xffffffffu, sum1, off);
        sq1  += __shfl_down_sync(0xffffffffu, sq1,  off);
    }
    if (lane == 0) {
        sh[0][wid] = sum0; sh[1][wid] = sq0;
        sh[2][wid] = sum1; sh[3][wid] = sq1;
    }
    __syncthreads();
    __shared__ float fin[4];
    if (wid == 0) {
        float a = (lane < 8) ? sh[0][lane] : 0.f;
        float b = (lane < 8) ? sh[1][lane] : 0.f;
        float c = (lane < 8) ? sh[2][lane] : 0.f;
        float d = (lane < 8) ? sh[3][lane] : 0.f;
#pragma unroll
        for (int off = 4; off > 0; off >>= 1) {
            a += __shfl_down_sync(0xffffffffu, a, off);
            b += __shfl_down_sync(0xffffffffu, b, off);
            c += __shfl_down_sync(0xffffffffu, c, off);
            d += __shfl_down_sync(0xffffffffu, d, off);
        }
        if (lane == 0) { fin[0] = a; fin[1] = b; fin[2] = c; fin[3] = d; }
    }
    __syncthreads();

    float mu0 = fin[0] * (1.f / D);
    float var0 = fin[1] * (1.f / D) - mu0 * mu0;
    float rs0 = rsqrtf(var0 + 1e-5f);
    float mu1 = fin[2] * (1.f / D);
    float var1 = fin[3] * (1.f / D) - mu1 * mu1;
    float rs1 = rsqrtf(var1 + 1e-5f);

    const float* g0 = gamma + (size_t)e0 * D;
    const float* b0 = beta  + (size_t)e0 * D;
    const float* g1 = gamma + (size_t)e1 * D;
    const float* b1v = beta + (size_t)e1 * D;

#pragma unroll
    for (int i = 0; i < 4; i++) {
        int d = tid + i * 256;
        float o0 = (v0[i] - mu0) * rs0 * g0[d] + b0[d];
        float o1 = (v1[i] - mu1) * rs1 * g1[d] + b1v[d];
        out[(size_t)t * D + d] = p0 * o0 + p1 * o1;
    }
}

// ---------------- launch ----------------
extern "C" void kernel_launch(void* const* d_in, const int* in_sizes, int n_in,
                              void* d_out, int out_size) {
    const float* x        = (const float*)d_in[0];
    const float* router_w = (const float*)d_in[1];
    const float* router_b = (const float*)d_in[2];
    const float* w1       = (const float*)d_in[3];
    const float* b1       = (const float*)d_in[4];
    const float* w2       = (const float*)d_in[5];
    const float* b2       = (const float*)d_in[6];
    const float* gamma    = (const float*)d_in[7];
    const float* beta     = (const float*)d_in[8];

    float* out = (float*)d_out;
    float* out_logits = out + (size_t)T * D;

    static int configured = 0;
    if (!configured) {
        cudaFuncSetAttribute(moe_gemm<D, H, true, true, true>,
                             cudaFuncAttributeMaxDynamicSharedMemorySize, SMEM_DYN);
        cudaFuncSetAttribute(moe_gemm<H, D, false, false, false>,
                             cudaFuncAttributeMaxDynamicSharedMemorySize, SMEM_DYN);
        configured = 1;
    }

    __half* d_w1h; cudaGetSymbolAddress((void**)&d_w1h, g_w1h);
    __half* d_w2h; cudaGetSymbolAddress((void**)&d_w2h, g_w2h);

    int conv_blocks = (NW4 + 255) / 256;
    fused_prep_kernel<<<NROUTER_BLOCKS + conv_blocks, 256>>>(
        x, router_w, router_b,
        (const float4*)w1, (uint2*)d_w1h,
        out_logits);

    moe_gemm<D, H, true, true, true><<<dim3(H / BN, RTILES), NTHREADS, SMEM_DYN>>>(
        b1, (const float4*)w2, (uint2*)d_w2h);
    moe_gemm<H, D, false, false, false><<<dim3(D / BN, RTILES), NTHREADS, SMEM_DYN>>>(
        b2, nullptr, nullptr);
    combine_kernel<<<T, 256>>>(x, gamma, beta, out);
}

// round 12
// speedup vs baseline: 1.0354x; 1.0354x over previous
#include <cuda_runtime.h>
#include <cuda_fp16.h>
#include <math.h>
#include <stdint.h>

// ---------------- problem constants ----------------
#define E   8
#define D   1024
#define H   4096
#define TK  2
#define T   4096      // B*S

#define BM  128
#define BN  128
#define BK  64
#define PIPE 3
#define NTHREADS 128   // 4 warps, 2x2, warp tile 64x64

#define MAXROWS (T*TK + E*BM)   // 9216
#define ROWTILES (MAXROWS / BM) // 72

#define ASTR 72     // halves: 64 + 8 pad
#define BSTR 136    // halves: 128 + 8 pad
#define ASZ (BM * ASTR * 2)
#define BSZ (BK * BSTR * 2)
#define SMEM_DYN (PIPE*ASZ + PIPE*BSZ)   // 107520 B

#define NROUTER_BLOCKS 512
#define NW4 (E * D * H / 4)    // float4 per weight tensor = 8388608
#define CONV_PER_CTA 4096      // float4 of w2 converted per GEMM1 CTA

// ---------------- scratch ----------------
// g_count/g_fill zero-initialized at load; combine re-zeroes them every run.
__device__ int    g_count[E];
__device__ int    g_fill[E];
__device__ int    g_offs[E + 1];
__device__ int    g_tok[MAXROWS];
__device__ int    g_slot[T * TK];
__device__ int    g_texp[T * TK];
__device__ float  g_tprob[T * TK];
__device__ __half g_xh[(size_t)T * D];
__device__ __half g_w1h[(size_t)E * D * H];
__device__ __half g_w2h[(size_t)E * H * D];
__device__ __half g_h1[(size_t)MAXROWS * H];
__device__ float  g_y [(size_t)MAXROWS * D];

// ---------------- helpers ----------------
static __device__ __forceinline__ uint32_t smem_u32(const void* p) {
    uint32_t a;
    asm("{ .reg .u64 t; cvta.to.shared.u64 t, %1; cvt.u32.u64 %0, t; }"
        : "=r"(a) : "l"(p));
    return a;
}
static __device__ __forceinline__ void cp_async16(uint32_t saddr, const void* gaddr) {
    asm volatile("cp.async.cg.shared.global [%0], [%1], 16;"
                 :: "r"(saddr), "l"(gaddr));
}
#define LDSM_X4(r0,r1,r2,r3,addr) \
    asm volatile("ldmatrix.sync.aligned.m8n8.x4.shared.b16 {%0,%1,%2,%3}, [%4];" \
                 : "=r"(r0), "=r"(r1), "=r"(r2), "=r"(r3) : "r"(addr))
#define LDSM_X4T(r0,r1,r2,r3,addr) \
    asm volatile("ldmatrix.sync.aligned.m8n8.x4.trans.shared.b16 {%0,%1,%2,%3}, [%4];" \
                 : "=r"(r0), "=r"(r1), "=r"(r2), "=r"(r3) : "r"(addr))

static __device__ __forceinline__ void mma_f16(float* d,
                                               const uint32_t* a,
                                               const uint32_t* b) {
    asm volatile(
        "mma.sync.aligned.m16n8k16.row.col.f32.f16.f16.f32 "
        "{%0,%1,%2,%3}, {%4,%5,%6,%7}, {%8,%9}, {%0,%1,%2,%3};"
        : "+f"(d[0]), "+f"(d[1]), "+f"(d[2]), "+f"(d[3])
        : "r"(a[0]), "r"(a[1]), "r"(a[2]), "r"(a[3]), "r"(b[0]), "r"(b[1]));
}
static __device__ __forceinline__ uint2 f4_to_h4(float4 v) {
    __half2 a = __float22half2_rn(make_float2(v.x, v.y));
    __half2 b = __float22half2_rn(make_float2(v.z, v.w));
    return make_uint2(*(uint32_t*)&a, *(uint32_t*)&b);
}

// ---------------- fused router + w1 conversion ----------------
__global__ void __launch_bounds__(256)
fused_prep_kernel(const float* __restrict__ x,
                  const float* __restrict__ rw,
                  const float* __restrict__ rb,
                  const float4* __restrict__ w1s, uint2* __restrict__ w1d,
                  float* __restrict__ out_logits) {
    if (blockIdx.x >= NROUTER_BLOCKS) {
        int i = (blockIdx.x - NROUTER_BLOCKS) * blockDim.x + threadIdx.x;
        if (i < NW4) w1d[i] = f4_to_h4(w1s[i]);
        return;
    }

    int warp = threadIdx.x >> 5;
    int lane = threadIdx.x & 31;
    int t = blockIdx.x * 8 + warp;
    if (t >= T) return;

    const float* xt = x + (size_t)t * D;
    __half* xh = g_xh + (size_t)t * D;
    float acc[E];
#pragma unroll
    for (int e = 0; e < E; e++) acc[e] = 0.f;
#pragma unroll 4
    for (int i = 0; i < D / 64; i++) {
        int k = i * 64 + lane * 2;
        float2 xv = *(const float2*)(xt + k);
        *(__half2*)(xh + k) = __float22half2_rn(xv);
        const float* r0 = rw + (size_t)k * E;
#pragma unroll
        for (int e = 0; e < E; e++) acc[e] += xv.x * r0[e] + xv.y * r0[E + e];
    }
#pragma unroll
    for (int off = 16; off > 0; off >>= 1)
#pragma unroll
        for (int e = 0; e < E; e++)
            acc[e] += __shfl_down_sync(0xffffffffu, acc[e], off);

    if (lane == 0) {
        float l[E];
#pragma unroll
        for (int e = 0; e < E; e++) {
            l[e] = acc[e] + rb[e];
            out_logits[(size_t)t * E + e] = l[e];
        }
        int i0 = 0;
#pragma unroll
        for (int e = 1; e < E; e++) if (l[e] > l[i0]) i0 = e;
        int i1 = -1;
#pragma unroll
        for (int e = 0; e < E; e++) {
            if (e == i0) continue;
            if (i1 < 0 || l[e] > l[i1]) i1 = e;
        }
        float m = l[i0], s = 0.f;
#pragma unroll
        for (int e = 0; e < E; e++) s += expf(l[e] - m);
        float p0 = expf(l[i0] - m) / s;
        float p1 = expf(l[i1] - m) / s;
        float inv = 1.f / (p0 + p1);
        p0 *= inv; p1 *= inv;

        g_texp[t * 2 + 0] = i0;  g_texp[t * 2 + 1] = i1;
        g_tprob[t * 2 + 0] = p0; g_tprob[t * 2 + 1] = p1;
        atomicAdd(&g_count[i0], 1);
        atomicAdd(&g_count[i1], 1);
    }
}

// ---------------- scatter (setup folded in) ----------------
// Each block recomputes the BM-aligned offsets from g_count locally,
// scatters its tokens, and zero-fills a stripe of the pad slots.
__global__ void __launch_bounds__(256)
scatter_kernel() {
    int tid = threadIdx.x;
    int gid = blockIdx.x * blockDim.x + tid;

    int cnt[E], offs[E + 1];
    int off = 0;
#pragma unroll
    for (int e = 0; e < E; e++) {
        cnt[e] = g_count[e];
        offs[e] = off;
        off += ((cnt[e] + BM - 1) / BM) * BM;
    }
    offs[E] = off;

    if (blockIdx.x == 0 && tid == 0) {
#pragma unroll
        for (int e = 0; e <= E; e++) g_offs[e] = offs[e];
    }

    // token scatter
    int t = gid;
    if (t < T) {
#pragma unroll
        for (int k = 0; k < TK; k++) {
            int e = g_texp[t * 2 + k];
            int pos = offs[e] + atomicAdd(&g_fill[e], 1);
            g_tok[pos] = t;
            g_slot[t * 2 + k] = pos;
        }
    }

    // pad-slot init (disjoint from scattered range)
#pragma unroll
    for (int e = 0; e < E; e++) {
        int start = offs[e] + cnt[e];
        int n = offs[e + 1] - start;
        for (int j = gid; j < n; j += T)
            g_tok[start + j] = 0;
    }
}

// ---------------- fp16 mma.sync grouped GEMM (frozen R10 mainloop) ----------------
template<int KTOT, int NLD, bool GELU, bool GATHER, bool CONV>
__global__ void __launch_bounds__(NTHREADS, 2)
moe_gemm(const float* __restrict__ bias,
         const float4* __restrict__ cvs, uint2* __restrict__ cvd) {
    const __half* Aall = GATHER ? g_xh : g_h1;
    const __half* Ball = GELU ? g_w1h : g_w2h;

    int tid = threadIdx.x;
    int cbase;
    if (CONV) cbase = (blockIdx.y * gridDim.x + blockIdx.x) * CONV_PER_CTA;

    int row0 = blockIdx.y * BM;
    if (row0 >= g_offs[E]) {
        if (CONV) {
#pragma unroll 4
            for (int j = 0; j < 32; j++) {
                int k = cbase + j * NTHREADS + tid;
                if (k < NW4) cvd[k] = f4_to_h4(cvs[k]);
            }
        }
        return;
    }
    int e = 0;
#pragma unroll
    for (int i = 1; i < E; i++) if (row0 >= g_offs[i]) e = i;
    int col0 = blockIdx.x * BN;
    const __half* Bexp = Ball + (size_t)e * KTOT * NLD + col0;

    extern __shared__ __align__(16) char dsm[];
    __shared__ int s_tok[BM];

    int wid = tid >> 5, lane = tid & 31;
    int wm = wid & 1, wn = wid >> 1;
    int g = lane >> 2, tg = lane & 3;
    int l15 = lane & 15, l16 = (lane >> 4) * 8;

    if (GATHER) s_tok[tid] = g_tok[row0 + tid];
    __syncthreads();

    uint32_t sAb = smem_u32(dsm);
    uint32_t sBb = sAb + PIPE * ASZ;

    const __half* a_gptr[8];
#pragma unroll
    for (int i = 0; i < 8; i++) {
        int idx = tid + i * NTHREADS;
        int r = idx >> 3, c = idx & 7;
        int rowid = GATHER ? s_tok[r] : (row0 + r);
        a_gptr[i] = Aall + (size_t)rowid * KTOT + c * 8;
    }
    const __half* b_gptr[8];
#pragma unroll
    for (int i = 0; i < 8; i++) {
        int idx = tid + i * NTHREADS;
        b_gptr[i] = Bexp + (size_t)(idx >> 4) * NLD + (idx & 15) * 8;
    }

    auto issue_copy = [&](int chunk, int buf) {
        uint32_t sa = sAb + buf * ASZ;
        uint32_t sb = sBb + buf * BSZ;
        int k0 = chunk * BK;
#pragma unroll
        for (int i = 0; i < 8; i++) {
            int idx = tid + i * NTHREADS;
            int r = idx >> 3, c = idx & 7;
            cp_async16(sa + (uint32_t)(r * ASTR + c * 8) * 2, a_gptr[i] + k0);
        }
#pragma unroll
        for (int i = 0; i < 8; i++) {
            int idx = tid + i * NTHREADS;
            int r = idx >> 4, c = idx & 15;
            cp_async16(sb + (uint32_t)(r * BSTR + c * 8) * 2,
                       b_gptr[i] + (size_t)k0 * NLD);
        }
        asm volatile("cp.async.commit_group;" ::: "memory");
    };

    float acc[4][8][4];
#pragma unroll
    for (int mf = 0; mf < 4; mf++)
#pragma unroll
        for (int nf = 0; nf < 8; nf++)
#pragma unroll
            for (int r = 0; r < 4; r++) acc[mf][nf][r] = 0.f;

    const int NC = KTOT / BK;   // 16 (gemm1) / 64 (gemm2)

    float4 cv0, cv1;
    if (CONV) {
        int k0 = cbase + tid, k1 = k0 + NTHREADS;
        if (k0 < NW4) cv0 = cvs[k0];
        if (k1 < NW4) cv1 = cvs[k1];
    }

    issue_copy(0, 0);
    issue_copy(1, 1);

    int buf = 0;
    for (int i = 0; i < NC; i++) {
        if (i + 1 < NC) asm volatile("cp.async.wait_group 1;" ::: "memory");
        else            asm volatile("cp.async.wait_group 0;" ::: "memory");
        __syncthreads();

        if (CONV) {
            int k0 = cbase + i * 2 * NTHREADS + tid;
            int k1 = k0 + NTHREADS;
            if (k0 < NW4) cvd[k0] = f4_to_h4(cv0);
            if (k1 < NW4) cvd[k1] = f4_to_h4(cv1);
            if (i + 1 < NC) {
                int n0 = k0 + 2 * NTHREADS, n1 = k1 + 2 * NTHREADS;
                if (n0 < NW4) cv0 = cvs[n0];
                if (n1 < NW4) cv1 = cvs[n1];
            }
        }

        if (i + 2 < NC) {
            int nb = buf + 2; if (nb >= PIPE) nb -= PIPE;
            issue_copy(i + 2, nb);
        }

        uint32_t sa = sAb + buf * ASZ;
        uint32_t sb = sBb + buf * BSZ;

#pragma unroll
        for (int kk = 0; kk < BK / 16; kk++) {
            uint32_t af[4][4];
#pragma unroll
            for (int mf = 0; mf < 4; mf++) {
                uint32_t addr = sa + (uint32_t)((wm * 64 + mf * 16 + l15) * ASTR
                                                + kk * 16 + l16) * 2;
                LDSM_X4(af[mf][0], af[mf][1], af[mf][2], af[mf][3], addr);
            }
            uint32_t bf[8][2];
#pragma unroll
            for (int pf = 0; pf < 4; pf++) {
                uint32_t addr = sb + (uint32_t)((kk * 16 + l15) * BSTR
                                                + wn * 64 + pf * 16 + l16) * 2;
                uint32_t r0, r1, r2, r3;
                LDSM_X4T(r0, r1, r2, r3, addr);
                bf[pf * 2][0] = r0;     bf[pf * 2][1] = r1;
                bf[pf * 2 + 1][0] = r2; bf[pf * 2 + 1][1] = r3;
            }
#pragma unroll
            for (int mf = 0; mf < 4; mf++)
#pragma unroll
                for (int nf = 0; nf < 8; nf++)
                    mma_f16(acc[mf][nf], af[mf], bf[nf]);
        }
        buf++; if (buf >= PIPE) buf -= PIPE;
    }

    // epilogue
    const float* be = bias + (size_t)e * NLD + col0 + wn * 64;
#pragma unroll
    for (int mf = 0; mf < 4; mf++) {
        int r0 = row0 + wm * 64 + mf * 16 + g;
#pragma unroll
        for (int nf = 0; nf < 8; nf++) {
            int cl = nf * 8 + tg * 2;
            float b0 = be[cl], b1 = be[cl + 1];
            float v0 = acc[mf][nf][0] + b0;
            float v1 = acc[mf][nf][1] + b1;
            float v2 = acc[mf][nf][2] + b0;
            float v3 = acc[mf][nf][3] + b1;
            int c = col0 + wn * 64 + cl;
            if (GELU) {
                const float kk = 0.70710678118654752440f;
                v0 = 0.5f * v0 * (1.f + erff(v0 * kk));
                v1 = 0.5f * v1 * (1.f + erff(v1 * kk));
                v2 = 0.5f * v2 * (1.f + erff(v2 * kk));
                v3 = 0.5f * v3 * (1.f + erff(v3 * kk));
                __half2 h01 = __float22half2_rn(make_float2(v0, v1));
                __half2 h23 = __float22half2_rn(make_float2(v2, v3));
                *(__half2*)(g_h1 + (size_t)r0 * NLD + c)       = h01;
                *(__half2*)(g_h1 + (size_t)(r0 + 8) * NLD + c) = h23;
            } else {
                *(float2*)(g_y + (size_t)r0 * NLD + c)       = make_float2(v0, v1);
                *(float2*)(g_y + (size_t)(r0 + 8) * NLD + c) = make_float2(v2, v3);
            }
        }
    }
}

// ---------------- combine (+counter re-zero for next replay) ----------------
__global__ void __launch_bounds__(256)
combine_kernel(const float* __restrict__ x,
               const float* __restrict__ gamma,
               const float* __restrict__ beta,
               float* __restrict__ out) {
    int t = blockIdx.x;
    int tid = threadIdx.x;

    if (blockIdx.x == 0 && tid < E) { g_count[tid] = 0; g_fill[tid] = 0; }

    int s0 = g_slot[t * 2 + 0], s1 = g_slot[t * 2 + 1];
    int e0 = g_texp[t * 2 + 0], e1 = g_texp[t * 2 + 1];
    float p0 = g_tprob[t * 2 + 0], p1 = g_tprob[t * 2 + 1];

    const float* y0 = g_y + (size_t)s0 * D;
    const float* y1 = g_y + (size_t)s1 * D;
    const float* xt = x + (size_t)t * D;

    float v0[4], v1[4];
    float sum0 = 0.f, sq0 = 0.f, sum1 = 0.f, sq1 = 0.f;
#pragma unroll
    for (int i = 0; i < 4; i++) {
        int d = tid + i * 256;
        float xv = xt[d];
        v0[i] = y0[d] + xv;
        v1[i] = y1[d] + xv;
        sum0 += v0[i]; sq0 += v0[i] * v0[i];
        sum1 += v1[i]; sq1 += v1[i] * v1[i];
    }

    __shared__ float sh[4][8];
    int lane = tid & 31, wid = tid >> 5;
#pragma unroll
    for (int off = 16; off > 0; off >>= 1) {
        sum0 += __shfl_down_sync(0xffffffffu, sum0, off);
        sq0  += __shfl_down_sync(0xffffffffu, sq0,  off);
        sum1 += __shfl_down_sync(0xffffffffu, sum1, off);
        sq1  += __shfl_down_sync(0xffffffffu, sq1,  off);
    }
    if (lane == 0) {
        sh[0][wid] = sum0; sh[1][wid] = sq0;
        sh[2][wid] = sum1; sh[3][wid] = sq1;
    }
    __syncthreads();
    __shared__ float fin[4];
    if (wid == 0) {
        float a = (lane < 8) ? sh[0][lane] : 0.f;
        float b = (lane < 8) ? sh[1][lane] : 0.f;
        float c = (lane < 8) ? sh[2][lane] : 0.f;
        float d = (lane < 8) ? sh[3][lane] : 0.f;
#pragma unroll
        for (int off = 4; off > 0; off >>= 1) {
            a += __shfl_down_sync(0xffffffffu, a, off);
            b += __shfl_down_sync(0xffffffffu, b, off);
            c += __shfl_down_sync(0xffffffffu, c, off);
            d += __shfl_down_sync(0xffffffffu, d, off);
        }
        if (lane == 0) { fin[0] = a; fin[1] = b; fin[2] = c; fin[3] = d; }
    }
    __syncthreads();

    float mu0 = fin[0] * (1.f / D);
    float var0 = fin[1] * (1.f / D) - mu0 * mu0;
    float rs0 = rsqrtf(var0 + 1e-5f);
    float mu1 = fin[2] * (1.f / D);
    float var1 = fin[3] * (1.f / D) - mu1 * mu1;
    float rs1 = rsqrtf(var1 + 1e-5f);

    const float* g0 = gamma + (size_t)e0 * D;
    const float* b0 = beta  + (size_t)e0 * D;
    const float* g1 = gamma + (size_t)e1 * D;
    const float* b1v = beta + (size_t)e1 * D;

#pragma unroll
    for (int i = 0; i < 4; i++) {
        int d = tid + i * 256;
        float o0 = (v0[i] - mu0) * rs0 * g0[d] + b0[d];
        float o1 = (v1[i] - mu1) * rs1 * g1[d] + b1v[d];
        out[(size_t)t * D + d] = p0 * o0 + p1 * o1;
    }
}

// ---------------- launch ----------------
extern "C" void kernel_launch(void* const* d_in, const int* in_sizes, int n_in,
                              void* d_out, int out_size) {
    const float* x        = (const float*)d_in[0];
    const float* router_w = (const float*)d_in[1];
    const float* router_b = (const float*)d_in[2];
    const float* w1       = (const float*)d_in[3];
    const float* b1       = (const float*)d_in[4];
    const float* w2       = (const float*)d_in[5];
    const float* b2       = (const float*)d_in[6];
    const float* gamma    = (const float*)d_in[7];
    const float* beta     = (const float*)d_in[8];

    float* out = (float*)d_out;
    float* out_logits = out + (size_t)T * D;

    static int configured = 0;
    if (!configured) {
        cudaFuncSetAttribute(moe_gemm<D, H, true, true, true>,
                             cudaFuncAttributeMaxDynamicSharedMemorySize, SMEM_DYN);
        cudaFuncSetAttribute(moe_gemm<H, D, false, false, false>,
                             cudaFuncAttributeMaxDynamicSharedMemorySize, SMEM_DYN);
        configured = 1;
    }

    __half* d_w1h; cudaGetSymbolAddress((void**)&d_w1h, g_w1h);
    __half* d_w2h; cudaGetSymbolAddress((void**)&d_w2h, g_w2h);

    int conv_blocks = (NW4 + 255) / 256;
    fused_prep_kernel<<<NROUTER_BLOCKS + conv_blocks, 256>>>(
        x, router_w, router_b,
        (const float4*)w1, (uint2*)d_w1h,
        out_logits);

    scatter_kernel<<<T / 256, 256>>>();
    moe_gemm<D, H, true, true, true><<<dim3(H / BN, ROWTILES), NTHREADS, SMEM_DYN>>>(
        b1, (const float4*)w2, (uint2*)d_w2h);
    moe_gemm<H, D, false, false, false><<<dim3(D / BN, ROWTILES), NTHREADS, SMEM_DYN>>>(
        b2, nullptr, nullptr);
    combine_kernel<<<T, 256>>>(x, gamma, beta, out);
}

// round 13
// speedup vs baseline: 1.0391x; 1.0035x over previous
#include <cuda_runtime.h>
#include <cuda_fp16.h>
#include <math.h>
#include <stdint.h>

// ---------------- problem constants ----------------
#define E   8
#define D   1024
#define H   4096
#define TK  2
#define T   4096      // B*S

#define BM  128
#define BN  128
#define BK  64
#define PIPE 3
#define NTHREADS 128   // 4 warps, 2x2, warp tile 64x64

#define MAXROWS (T*TK + E*BM)   // 9216
#define ROWTILES (MAXROWS / BM) // 72

#define ASTR 72     // halves: 64 + 8 pad
#define BSTR 136    // halves: 128 + 8 pad
#define ASZ (BM * ASTR * 2)
#define BSZ (BK * BSTR * 2)
#define SMEM_DYN (PIPE*ASZ + PIPE*BSZ)   // 107520 B

#define NROUTER_BLOCKS 512
#define NW4 (E * D * H / 4)    // float4 per weight tensor = 8388608
#define CONV_PER_CTA 4096      // float4 of w2 converted per GEMM1 CTA

// ---------------- scratch ----------------
__device__ int    g_count[E];
__device__ int    g_fill[E];
__device__ int    g_offs[E + 1];
__device__ int    g_tok[MAXROWS];
__device__ int    g_slot[T * TK];
__device__ int    g_texp[T * TK];
__device__ float  g_tprob[T * TK];
__device__ __half g_xh[(size_t)T * D];
__device__ __half g_w1h[(size_t)E * D * H];
__device__ __half g_w2h[(size_t)E * H * D];
__device__ __half g_h1[(size_t)MAXROWS * H];
__device__ float  g_y [(size_t)MAXROWS * D];

// ---------------- helpers ----------------
static __device__ __forceinline__ uint32_t smem_u32(const void* p) {
    uint32_t a;
    asm("{ .reg .u64 t; cvta.to.shared.u64 t, %1; cvt.u32.u64 %0, t; }"
        : "=r"(a) : "l"(p));
    return a;
}
static __device__ __forceinline__ void cp_async16(uint32_t saddr, const void* gaddr) {
    asm volatile("cp.async.cg.shared.global [%0], [%1], 16;"
                 :: "r"(saddr), "l"(gaddr));
}
static __device__ __forceinline__ void grid_dep_sync() {
    asm volatile("griddepcontrol.wait;" ::: "memory");
}
static __device__ __forceinline__ void grid_dep_trigger() {
    asm volatile("griddepcontrol.launch_dependents;" ::: "memory");
}
#define LDSM_X4(r0,r1,r2,r3,addr) \
    asm volatile("ldmatrix.sync.aligned.m8n8.x4.shared.b16 {%0,%1,%2,%3}, [%4];" \
                 : "=r"(r0), "=r"(r1), "=r"(r2), "=r"(r3) : "r"(addr))
#define LDSM_X4T(r0,r1,r2,r3,addr) \
    asm volatile("ldmatrix.sync.aligned.m8n8.x4.trans.shared.b16 {%0,%1,%2,%3}, [%4];" \
                 : "=r"(r0), "=r"(r1), "=r"(r2), "=r"(r3) : "r"(addr))

static __device__ __forceinline__ void mma_f16(float* d,
                                               const uint32_t* a,
                                               const uint32_t* b) {
    asm volatile(
        "mma.sync.aligned.m16n8k16.row.col.f32.f16.f16.f32 "
        "{%0,%1,%2,%3}, {%4,%5,%6,%7}, {%8,%9}, {%0,%1,%2,%3};"
        : "+f"(d[0]), "+f"(d[1]), "+f"(d[2]), "+f"(d[3])
        : "r"(a[0]), "r"(a[1]), "r"(a[2]), "r"(a[3]), "r"(b[0]), "r"(b[1]));
}
static __device__ __forceinline__ uint2 f4_to_h4(float4 v) {
    __half2 a = __float22half2_rn(make_float2(v.x, v.y));
    __half2 b = __float22half2_rn(make_float2(v.z, v.w));
    return make_uint2(*(uint32_t*)&a, *(uint32_t*)&b);
}

// ---------------- fused router + w1 conversion ----------------
__global__ void __launch_bounds__(256)
fused_prep_kernel(const float* __restrict__ x,
                  const float* __restrict__ rw,
                  const float* __restrict__ rb,
                  const float4* __restrict__ w1s, uint2* __restrict__ w1d,
                  float* __restrict__ out_logits) {
    if (blockIdx.x >= NROUTER_BLOCKS) {
        // depends only on inputs — no grid-dep wait needed
        int i = (blockIdx.x - NROUTER_BLOCKS) * blockDim.x + threadIdx.x;
        if (i < NW4) w1d[i] = f4_to_h4(w1s[i]);
        grid_dep_trigger();
        return;
    }

    grid_dep_sync();   // cross-replay: combine of previous replay zeroes g_count

    int warp = threadIdx.x >> 5;
    int lane = threadIdx.x & 31;
    int t = blockIdx.x * 8 + warp;
    if (t >= T) { grid_dep_trigger(); return; }

    const float* xt = x + (size_t)t * D;
    __half* xh = g_xh + (size_t)t * D;
    float acc[E];
#pragma unroll
    for (int e = 0; e < E; e++) acc[e] = 0.f;
#pragma unroll 4
    for (int i = 0; i < D / 64; i++) {
        int k = i * 64 + lane * 2;
        float2 xv = *(const float2*)(xt + k);
        *(__half2*)(xh + k) = __float22half2_rn(xv);
        const float* r0 = rw + (size_t)k * E;
#pragma unroll
        for (int e = 0; e < E; e++) acc[e] += xv.x * r0[e] + xv.y * r0[E + e];
    }
#pragma unroll
    for (int off = 16; off > 0; off >>= 1)
#pragma unroll
        for (int e = 0; e < E; e++)
            acc[e] += __shfl_down_sync(0xffffffffu, acc[e], off);

    if (lane == 0) {
        float l[E];
#pragma unroll
        for (int e = 0; e < E; e++) {
            l[e] = acc[e] + rb[e];
            out_logits[(size_t)t * E + e] = l[e];
        }
        int i0 = 0;
#pragma unroll
        for (int e = 1; e < E; e++) if (l[e] > l[i0]) i0 = e;
        int i1 = -1;
#pragma unroll
        for (int e = 0; e < E; e++) {
            if (e == i0) continue;
            if (i1 < 0 || l[e] > l[i1]) i1 = e;
        }
        float m = l[i0], s = 0.f;
#pragma unroll
        for (int e = 0; e < E; e++) s += expf(l[e] - m);
        float p0 = expf(l[i0] - m) / s;
        float p1 = expf(l[i1] - m) / s;
        float inv = 1.f / (p0 + p1);
        p0 *= inv; p1 *= inv;

        g_texp[t * 2 + 0] = i0;  g_texp[t * 2 + 1] = i1;
        g_tprob[t * 2 + 0] = p0; g_tprob[t * 2 + 1] = p1;
        atomicAdd(&g_count[i0], 1);
        atomicAdd(&g_count[i1], 1);
    }
    grid_dep_trigger();
}

// ---------------- scatter (setup folded in) ----------------
__global__ void __launch_bounds__(256)
scatter_kernel() {
    grid_dep_sync();   // wait for router counts

    int tid = threadIdx.x;
    int gid = blockIdx.x * blockDim.x + tid;

    int cnt[E], offs[E + 1];
    int off = 0;
#pragma unroll
    for (int e = 0; e < E; e++) {
        cnt[e] = g_count[e];
        offs[e] = off;
        off += ((cnt[e] + BM - 1) / BM) * BM;
    }
    offs[E] = off;

    if (blockIdx.x == 0 && tid == 0) {
#pragma unroll
        for (int e = 0; e <= E; e++) g_offs[e] = offs[e];
    }

    int t = gid;
    if (t < T) {
#pragma unroll
        for (int k = 0; k < TK; k++) {
            int e = g_texp[t * 2 + k];
            int pos = offs[e] + atomicAdd(&g_fill[e], 1);
            g_tok[pos] = t;
            g_slot[t * 2 + k] = pos;
        }
    }

#pragma unroll
    for (int e = 0; e < E; e++) {
        int start = offs[e] + cnt[e];
        int n = offs[e + 1] - start;
        for (int j = gid; j < n; j += T)
            g_tok[start + j] = 0;
    }
    grid_dep_trigger();
}

// ---------------- fp16 mma.sync grouped GEMM (frozen R10 mainloop + PDL) ----------------
template<int KTOT, int NLD, bool GELU, bool GATHER, bool CONV>
__global__ void __launch_bounds__(NTHREADS, 2)
moe_gemm(const float* __restrict__ bias,
         const float4* __restrict__ cvs, uint2* __restrict__ cvd) {
    const __half* Aall = GATHER ? g_xh : g_h1;
    const __half* Ball = GELU ? g_w1h : g_w2h;

    int tid = threadIdx.x;
    int cbase;
    float4 cv0, cv1;
    if (CONV) {
        // conv source depends only on kernel inputs — prefetch BEFORE grid sync
        cbase = (blockIdx.y * gridDim.x + blockIdx.x) * CONV_PER_CTA;
        int k0 = cbase + tid, k1 = k0 + NTHREADS;
        if (k0 < NW4) cv0 = cvs[k0];
        if (k1 < NW4) cv1 = cvs[k1];
    }

    grid_dep_sync();   // wait for scatter (g_offs/g_tok) / gemm1 (g_h1)

    int row0 = blockIdx.y * BM;
    if (row0 >= g_offs[E]) {
        if (CONV) {
            if (cbase + tid < NW4) cvd[cbase + tid] = f4_to_h4(cv0);
            if (cbase + NTHREADS + tid < NW4) cvd[cbase + NTHREADS + tid] = f4_to_h4(cv1);
#pragma unroll 4
            for (int j = 2; j < 32; j++) {
                int k = cbase + j * NTHREADS + tid;
                if (k < NW4) cvd[k] = f4_to_h4(cvs[k]);
            }
        }
        grid_dep_trigger();
        return;
    }
    int e = 0;
#pragma unroll
    for (int i = 1; i < E; i++) if (row0 >= g_offs[i]) e = i;
    int col0 = blockIdx.x * BN;
    const __half* Bexp = Ball + (size_t)e * KTOT * NLD + col0;

    extern __shared__ __align__(16) char dsm[];
    __shared__ int s_tok[BM];

    int wid = tid >> 5, lane = tid & 31;
    int wm = wid & 1, wn = wid >> 1;
    int g = lane >> 2, tg = lane & 3;
    int l15 = lane & 15, l16 = (lane >> 4) * 8;

    if (GATHER) s_tok[tid] = g_tok[row0 + tid];
    __syncthreads();

    uint32_t sAb = smem_u32(dsm);
    uint32_t sBb = sAb + PIPE * ASZ;

    const __half* a_gptr[8];
#pragma unroll
    for (int i = 0; i < 8; i++) {
        int idx = tid + i * NTHREADS;
        int r = idx >> 3, c = idx & 7;
        int rowid = GATHER ? s_tok[r] : (row0 + r);
        a_gptr[i] = Aall + (size_t)rowid * KTOT + c * 8;
    }
    const __half* b_gptr[8];
#pragma unroll
    for (int i = 0; i < 8; i++) {
        int idx = tid + i * NTHREADS;
        b_gptr[i] = Bexp + (size_t)(idx >> 4) * NLD + (idx & 15) * 8;
    }

    auto issue_copy = [&](int chunk, int buf) {
        uint32_t sa = sAb + buf * ASZ;
        uint32_t sb = sBb + buf * BSZ;
        int k0 = chunk * BK;
#pragma unroll
        for (int i = 0; i < 8; i++) {
            int idx = tid + i * NTHREADS;
            int r = idx >> 3, c = idx & 7;
            cp_async16(sa + (uint32_t)(r * ASTR + c * 8) * 2, a_gptr[i] + k0);
        }
#pragma unroll
        for (int i = 0; i < 8; i++) {
            int idx = tid + i * NTHREADS;
            int r = idx >> 4, c = idx & 15;
            cp_async16(sb + (uint32_t)(r * BSTR + c * 8) * 2,
                       b_gptr[i] + (size_t)k0 * NLD);
        }
        asm volatile("cp.async.commit_group;" ::: "memory");
    };

    float acc[4][8][4];
#pragma unroll
    for (int mf = 0; mf < 4; mf++)
#pragma unroll
        for (int nf = 0; nf < 8; nf++)
#pragma unroll
            for (int r = 0; r < 4; r++) acc[mf][nf][r] = 0.f;

    const int NC = KTOT / BK;   // 16 (gemm1) / 64 (gemm2)

    issue_copy(0, 0);
    issue_copy(1, 1);

    int buf = 0;
    for (int i = 0; i < NC; i++) {
        if (i + 1 < NC) asm volatile("cp.async.wait_group 1;" ::: "memory");
        else            asm volatile("cp.async.wait_group 0;" ::: "memory");
        __syncthreads();

        if (CONV) {
            int k0 = cbase + i * 2 * NTHREADS + tid;
            int k1 = k0 + NTHREADS;
            if (k0 < NW4) cvd[k0] = f4_to_h4(cv0);
            if (k1 < NW4) cvd[k1] = f4_to_h4(cv1);
            if (i + 1 < NC) {
                int n0 = k0 + 2 * NTHREADS, n1 = k1 + 2 * NTHREADS;
                if (n0 < NW4) cv0 = cvs[n0];
                if (n1 < NW4) cv1 = cvs[n1];
            }
        }

        if (i + 2 < NC) {
            int nb = buf + 2; if (nb >= PIPE) nb -= PIPE;
            issue_copy(i + 2, nb);
        }

        uint32_t sa = sAb + buf * ASZ;
        uint32_t sb = sBb + buf * BSZ;

#pragma unroll
        for (int kk = 0; kk < BK / 16; kk++) {
            uint32_t af[4][4];
#pragma unroll
            for (int mf = 0; mf < 4; mf++) {
                uint32_t addr = sa + (uint32_t)((wm * 64 + mf * 16 + l15) * ASTR
                                                + kk * 16 + l16) * 2;
                LDSM_X4(af[mf][0], af[mf][1], af[mf][2], af[mf][3], addr);
            }
            uint32_t bf[8][2];
#pragma unroll
            for (int pf = 0; pf < 4; pf++) {
                uint32_t addr = sb + (uint32_t)((kk * 16 + l15) * BSTR
                                                + wn * 64 + pf * 16 + l16) * 2;
                uint32_t r0, r1, r2, r3;
                LDSM_X4T(r0, r1, r2, r3, addr);
                bf[pf * 2][0] = r0;     bf[pf * 2][1] = r1;
                bf[pf * 2 + 1][0] = r2; bf[pf * 2 + 1][1] = r3;
            }
#pragma unroll
            for (int mf = 0; mf < 4; mf++)
#pragma unroll
                for (int nf = 0; nf < 8; nf++)
                    mma_f16(acc[mf][nf], af[mf], bf[nf]);
        }
        buf++; if (buf >= PIPE) buf -= PIPE;
    }

    grid_dep_trigger();

    // epilogue
    const float* be = bias + (size_t)e * NLD + col0 + wn * 64;
#pragma unroll
    for (int mf = 0; mf < 4; mf++) {
        int r0 = row0 + wm * 64 + mf * 16 + g;
#pragma unroll
        for (int nf = 0; nf < 8; nf++) {
            int cl = nf * 8 + tg * 2;
            float b0 = be[cl], b1 = be[cl + 1];
            float v0 = acc[mf][nf][0] + b0;
            float v1 = acc[mf][nf][1] + b1;
            float v2 = acc[mf][nf][2] + b0;
            float v3 = acc[mf][nf][3] + b1;
            int c = col0 + wn * 64 + cl;
            if (GELU) {
                const float kk = 0.70710678118654752440f;
                v0 = 0.5f * v0 * (1.f + erff(v0 * kk));
                v1 = 0.5f * v1 * (1.f + erff(v1 * kk));
                v2 = 0.5f * v2 * (1.f + erff(v2 * kk));
                v3 = 0.5f * v3 * (1.f + erff(v3 * kk));
                __half2 h01 = __float22half2_rn(make_float2(v0, v1));
                __half2 h23 = __float22half2_rn(make_float2(v2, v3));
                *(__half2*)(g_h1 + (size_t)r0 * NLD + c)       = h01;
                *(__half2*)(g_h1 + (size_t)(r0 + 8) * NLD + c) = h23;
            } else {
                *(float2*)(g_y + (size_t)r0 * NLD + c)       = make_float2(v0, v1);
                *(float2*)(g_y + (size_t)(r0 + 8) * NLD + c) = make_float2(v2, v3);
            }
        }
    }
}

// ---------------- combine (+counter re-zero for next replay) ----------------
__global__ void __launch_bounds__(256)
combine_kernel(const float* __restrict__ x,
               const float* __restrict__ gamma,
               const float* __restrict__ beta,
               float* __restrict__ out) {
    grid_dep_sync();

    int t = blockIdx.x;
    int tid = threadIdx.x;

    if (blockIdx.x == 0 && tid < E) { g_count[tid] = 0; g_fill[tid] = 0; }

    int s0 = g_slot[t * 2 + 0], s1 = g_slot[t * 2 + 1];
    int e0 = g_texp[t * 2 + 0], e1 = g_texp[t * 2 + 1];
    float p0 = g_tprob[t * 2 + 0], p1 = g_tprob[t * 2 + 1];

    const float* y0 = g_y + (size_t)s0 * D;
    const float* y1 = g_y + (size_t)s1 * D;
    const float* xt = x + (size_t)t * D;

    float v0[4], v1[4];
    float sum0 = 0.f, sq0 = 0.f, sum1 = 0.f, sq1 = 0.f;
#pragma unroll
    for (int i = 0; i < 4; i++) {
        int d = tid + i * 256;
        float xv = xt[d];
        v0[i] = y0[d] + xv;
        v1[i] = y1[d] + xv;
        sum0 += v0[i]; sq0 += v0[i] * v0[i];
        sum1 += v1[i]; sq1 += v1[i] * v1[i];
    }

    __shared__ float sh[4][8];
    int lane = tid & 31, wid = tid >> 5;
#pragma unroll
    for (int off = 16; off > 0; off >>= 1) {
        sum0 += __shfl_down_sync(0xffffffffu, sum0, off);
        sq0  += __shfl_down_sync(0xffffffffu, sq0,  off);
        sum1 += __shfl_down_sync(0xffffffffu, sum1, off);
        sq1  += __shfl_down_sync(0xffffffffu, sq1,  off);
    }
    if (lane == 0) {
        sh[0][wid] = sum0; sh[1][wid] = sq0;
        sh[2][wid] = sum1; sh[3][wid] = sq1;
    }
    __syncthreads();
    __shared__ float fin[4];
    if (wid == 0) {
        float a = (lane < 8) ? sh[0][lane] : 0.f;
        float b = (lane < 8) ? sh[1][lane] : 0.f;
        float c = (lane < 8) ? sh[2][lane] : 0.f;
        float d = (lane < 8) ? sh[3][lane] : 0.f;
#pragma unroll
        for (int off = 4; off > 0; off >>= 1) {
            a += __shfl_down_sync(0xffffffffu, a, off);
            b += __shfl_down_sync(0xffffffffu, b, off);
            c += __shfl_down_sync(0xffffffffu, c, off);
            d += __shfl_down_sync(0xffffffffu, d, off);
        }
        if (lane == 0) { fin[0] = a; fin[1] = b; fin[2] = c; fin[3] = d; }
    }
    __syncthreads();

    float mu0 = fin[0] * (1.f / D);
    float var0 = fin[1] * (1.f / D) - mu0 * mu0;
    float rs0 = rsqrtf(var0 + 1e-5f);
    float mu1 = fin[2] * (1.f / D);
    float var1 = fin[3] * (1.f / D) - mu1 * mu1;
    float rs1 = rsqrtf(var1 + 1e-5f);

    const float* g0 = gamma + (size_t)e0 * D;
    const float* b0 = beta  + (size_t)e0 * D;
    const float* g1 = gamma + (size_t)e1 * D;
    const float* b1v = beta + (size_t)e1 * D;

#pragma unroll
    for (int i = 0; i < 4; i++) {
        int d = tid + i * 256;
        float o0 = (v0[i] - mu0) * rs0 * g0[d] + b0[d];
        float o1 = (v1[i] - mu1) * rs1 * g1[d] + b1v[d];
        out[(size_t)t * D + d] = p0 * o0 + p1 * o1;
    }
    grid_dep_trigger();
}

// ---------------- launch helper with PDL attribute ----------------
template<typename... Args>
static void launch_pdl(void (*kern)(Args...), dim3 grid, dim3 block,
                       size_t smem, cudaStream_t stream, Args... args) {
    cudaLaunchAttribute attr[1];
    attr[0].id = cudaLaunchAttributeProgrammaticStreamSerialization;
    attr[0].val.programmaticStreamSerializationAllowed = 1;
    cudaLaunchConfig_t cfg = {};
    cfg.gridDim = grid;
    cfg.blockDim = block;
    cfg.dynamicSmemBytes = smem;
    cfg.stream = stream;
    cfg.attrs = attr;
    cfg.numAttrs = 1;
    cudaLaunchKernelEx(&cfg, kern, args...);
}

// ---------------- launch ----------------
extern "C" void kernel_launch(void* const* d_in, const int* in_sizes, int n_in,
                              void* d_out, int out_size) {
    const float* x        = (const float*)d_in[0];
    const float* router_w = (const float*)d_in[1];
    const float* router_b = (const float*)d_in[2];
    const float* w1       = (const float*)d_in[3];
    const float* b1       = (const float*)d_in[4];
    const float* w2       = (const float*)d_in[5];
    const float* b2       = (const float*)d_in[6];
    const float* gamma    = (const float*)d_in[7];
    const float* beta     = (const float*)d_in[8];

    float* out = (float*)d_out;
    float* out_logits = out + (size_t)T * D;

    static int configured = 0;
    if (!configured) {
        cudaFuncSetAttribute(moe_gemm<D, H, true, true, true>,
                             cudaFuncAttributeMaxDynamicSharedMemorySize, SMEM_DYN);
        cudaFuncSetAttribute(moe_gemm<H, D, false, false, false>,
                             cudaFuncAttributeMaxDynamicSharedMemorySize, SMEM_DYN);
        configured = 1;
    }

    __half* d_w1h; cudaGetSymbolAddress((void**)&d_w1h, g_w1h);
    __half* d_w2h; cudaGetSymbolAddress((void**)&d_w2h, g_w2h);

    cudaStream_t s = 0;

    int conv_blocks = (NW4 + 255) / 256;
    launch_pdl(fused_prep_kernel,
               dim3(NROUTER_BLOCKS + conv_blocks), dim3(256), 0, s,
               x, router_w, router_b,
               (const float4*)w1, (uint2*)d_w1h, out_logits);

    launch_pdl(scatter_kernel, dim3(T / 256), dim3(256), 0, s);

    launch_pdl(moe_gemm<D, H, true, true, true>,
               dim3(H / BN, ROWTILES), dim3(NTHREADS), (size_t)SMEM_DYN, s,
               b1, (const float4*)w2, (uint2*)d_w2h);
    launch_pdl(moe_gemm<H, D, false, false, false>,
               dim3(D / BN, ROWTILES), dim3(NTHREADS), (size_t)SMEM_DYN, s,
               b2, (const float4*)nullptr, (uint2*)nullptr);

    launch_pdl(combine_kernel, dim3(T), dim3(256), 0, s,
               x, gamma, beta, out);
}

// round 14
// speedup vs baseline: 1.0422x; 1.0029x over previous
#include <cuda_runtime.h>
#include <cuda_fp16.h>
#include <math.h>
#include <stdint.h>

// ---------------- problem constants ----------------
#define E   8
#define D   1024
#define H   4096
#define TK  2
#define T   4096      // B*S

#define BM  128
#define BN  128
#define BK  64
#define PIPE 3
#define NTHREADS 128   // 4 warps, 2x2, warp tile 64x64

#define MAXROWS (T*TK + E*BM)   // 9216
#define ROWTILES (MAXROWS / BM) // 72

#define ASTR 72     // halves: 64 + 8 pad
#define BSTR 136    // halves: 128 + 8 pad
#define ASZ (BM * ASTR * 2)
#define BSZ (BK * BSTR * 2)
#define SMEM_DYN (PIPE*ASZ + PIPE*BSZ)   // 107520 B

#define NROUTER_BLOCKS 512
#define NW4 (E * D * H / 4)    // float4 per weight tensor = 8388608 = 2^23
#define CONV_PER_CTA 4096      // float4 of w2 converted per GEMM1 CTA
#define SLAB_SHIFT 20          // NW4 / E = 2^20 float4 per expert slab

// ---------------- scratch ----------------
__device__ int    g_count[E];
__device__ int    g_fill[E];
__device__ int    g_offs[E + 1];
__device__ int    g_tok[MAXROWS];
__device__ int    g_slot[T * TK];
__device__ int    g_texp[T * TK];
__device__ float  g_tprob[T * TK];
__device__ int    g_done1[ROWTILES];   // gemm1 coltiles done per rowtile (target 32)
__device__ int    g_done2[ROWTILES];   // gemm2 coltiles done per rowtile (target 8)
__device__ int    g_conv[E];           // w2h slices converted per expert slab (target 256)
__device__ __half g_xh[(size_t)T * D];
__device__ __half g_w1h[(size_t)E * D * H];
__device__ __half g_w2h[(size_t)E * H * D];
__device__ __half g_h1[(size_t)MAXROWS * H];
__device__ float  g_y [(size_t)MAXROWS * D];

// ---------------- helpers ----------------
static __device__ __forceinline__ uint32_t smem_u32(const void* p) {
    uint32_t a;
    asm("{ .reg .u64 t; cvta.to.shared.u64 t, %1; cvt.u32.u64 %0, t; }"
        : "=r"(a) : "l"(p));
    return a;
}
static __device__ __forceinline__ void cp_async16(uint32_t saddr, const void* gaddr) {
    asm volatile("cp.async.cg.shared.global [%0], [%1], 16;"
                 :: "r"(saddr), "l"(gaddr));
}
static __device__ __forceinline__ void grid_dep_sync() {
    asm volatile("griddepcontrol.wait;" ::: "memory");
}
static __device__ __forceinline__ void grid_dep_trigger() {
    asm volatile("griddepcontrol.launch_dependents;" ::: "memory");
}
static __device__ __forceinline__ int ld_acquire(const int* p) {
    int v;
    asm volatile("ld.acquire.gpu.global.s32 %0, [%1];" : "=r"(v) : "l"(p));
    return v;
}
#define LDSM_X4(r0,r1,r2,r3,addr) \
    asm volatile("ldmatrix.sync.aligned.m8n8.x4.shared.b16 {%0,%1,%2,%3}, [%4];" \
                 : "=r"(r0), "=r"(r1), "=r"(r2), "=r"(r3) : "r"(addr))
#define LDSM_X4T(r0,r1,r2,r3,addr) \
    asm volatile("ldmatrix.sync.aligned.m8n8.x4.trans.shared.b16 {%0,%1,%2,%3}, [%4];" \
                 : "=r"(r0), "=r"(r1), "=r"(r2), "=r"(r3) : "r"(addr))

static __device__ __forceinline__ void mma_f16(float* d,
                                               const uint32_t* a,
                                               const uint32_t* b) {
    asm volatile(
        "mma.sync.aligned.m16n8k16.row.col.f32.f16.f16.f32 "
        "{%0,%1,%2,%3}, {%4,%5,%6,%7}, {%8,%9}, {%0,%1,%2,%3};"
        : "+f"(d[0]), "+f"(d[1]), "+f"(d[2]), "+f"(d[3])
        : "r"(a[0]), "r"(a[1]), "r"(a[2]), "r"(a[3]), "r"(b[0]), "r"(b[1]));
}
static __device__ __forceinline__ uint2 f4_to_h4(float4 v) {
    __half2 a = __float22half2_rn(make_float2(v.x, v.y));
    __half2 b = __float22half2_rn(make_float2(v.z, v.w));
    return make_uint2(*(uint32_t*)&a, *(uint32_t*)&b);
}

// ---------------- fused router + w1 conversion ----------------
__global__ void __launch_bounds__(256)
fused_prep_kernel(const float* __restrict__ x,
                  const float* __restrict__ rw,
                  const float* __restrict__ rb,
                  const float4* __restrict__ w1s, uint2* __restrict__ w1d,
                  float* __restrict__ out_logits) {
    if (blockIdx.x >= NROUTER_BLOCKS) {
        int i = (blockIdx.x - NROUTER_BLOCKS) * blockDim.x + threadIdx.x;
        if (i < NW4) w1d[i] = f4_to_h4(w1s[i]);
        grid_dep_trigger();
        return;
    }

    grid_dep_sync();   // previous replay's combine zeroed g_count

    int warp = threadIdx.x >> 5;
    int lane = threadIdx.x & 31;
    int t = blockIdx.x * 8 + warp;
    if (t >= T) { grid_dep_trigger(); return; }

    const float* xt = x + (size_t)t * D;
    __half* xh = g_xh + (size_t)t * D;
    float acc[E];
#pragma unroll
    for (int e = 0; e < E; e++) acc[e] = 0.f;
#pragma unroll 4
    for (int i = 0; i < D / 64; i++) {
        int k = i * 64 + lane * 2;
        float2 xv = *(const float2*)(xt + k);
        *(__half2*)(xh + k) = __float22half2_rn(xv);
        const float* r0 = rw + (size_t)k * E;
#pragma unroll
        for (int e = 0; e < E; e++) acc[e] += xv.x * r0[e] + xv.y * r0[E + e];
    }
#pragma unroll
    for (int off = 16; off > 0; off >>= 1)
#pragma unroll
        for (int e = 0; e < E; e++)
            acc[e] += __shfl_down_sync(0xffffffffu, acc[e], off);

    if (lane == 0) {
        float l[E];
#pragma unroll
        for (int e = 0; e < E; e++) {
            l[e] = acc[e] + rb[e];
            out_logits[(size_t)t * E + e] = l[e];
        }
        int i0 = 0;
#pragma unroll
        for (int e = 1; e < E; e++) if (l[e] > l[i0]) i0 = e;
        int i1 = -1;
#pragma unroll
        for (int e = 0; e < E; e++) {
            if (e == i0) continue;
            if (i1 < 0 || l[e] > l[i1]) i1 = e;
        }
        float m = l[i0], s = 0.f;
#pragma unroll
        for (int e = 0; e < E; e++) s += expf(l[e] - m);
        float p0 = expf(l[i0] - m) / s;
        float p1 = expf(l[i1] - m) / s;
        float inv = 1.f / (p0 + p1);
        p0 *= inv; p1 *= inv;

        g_texp[t * 2 + 0] = i0;  g_texp[t * 2 + 1] = i1;
        g_tprob[t * 2 + 0] = p0; g_tprob[t * 2 + 1] = p1;
        atomicAdd(&g_count[i0], 1);
        atomicAdd(&g_count[i1], 1);
    }
    grid_dep_trigger();
}

// ---------------- scatter (setup folded in, + flag reset) ----------------
__global__ void __launch_bounds__(256)
scatter_kernel() {
    grid_dep_sync();   // wait for router counts

    int tid = threadIdx.x;
    int gid = blockIdx.x * blockDim.x + tid;

    // reset producer/consumer flags for this run (ordered before GEMM1 via PDL)
    if (blockIdx.x == 0) {
        if (tid < ROWTILES) { g_done1[tid] = 0; g_done2[tid] = 0; }
        if (tid < E) g_conv[tid] = 0;
    }

    int cnt[E], offs[E + 1];
    int off = 0;
#pragma unroll
    for (int e = 0; e < E; e++) {
        cnt[e] = g_count[e];
        offs[e] = off;
        off += ((cnt[e] + BM - 1) / BM) * BM;
    }
    offs[E] = off;

    if (blockIdx.x == 0 && tid == 0) {
#pragma unroll
        for (int e = 0; e <= E; e++) g_offs[e] = offs[e];
    }

    int t = gid;
    if (t < T) {
#pragma unroll
        for (int k = 0; k < TK; k++) {
            int e = g_texp[t * 2 + k];
            int pos = offs[e] + atomicAdd(&g_fill[e], 1);
            g_tok[pos] = t;
            g_slot[t * 2 + k] = pos;
        }
    }

#pragma unroll
    for (int e = 0; e < E; e++) {
        int start = offs[e] + cnt[e];
        int n = offs[e + 1] - start;
        for (int j = gid; j < n; j += T)
            g_tok[start + j] = 0;
    }
    grid_dep_trigger();
}

// ---------------- fp16 mma.sync grouped GEMM (frozen mainloop + flags) ----------------
// GELU (gemm1): consumer sync via grid_dep_sync (scatter); produces g_done1/g_conv.
// !GELU (gemm2): consumer sync via spin on g_done1/g_conv; produces g_done2.
template<int KTOT, int NLD, bool GELU, bool GATHER, bool CONV>
__global__ void __launch_bounds__(NTHREADS, 2)
moe_gemm(const float* __restrict__ bias,
         const float4* __restrict__ cvs, uint2* __restrict__ cvd) {
    const __half* Aall = GATHER ? g_xh : g_h1;
    const __half* Ball = GELU ? g_w1h : g_w2h;

    int tid = threadIdx.x;
    int cbase = 0;
    float4 cv0, cv1;
    if (CONV) {
        cbase = (blockIdx.y * gridDim.x + blockIdx.x) * CONV_PER_CTA;
        int k0 = cbase + tid, k1 = k0 + NTHREADS;
        if (k0 < NW4) cv0 = cvs[k0];
        if (k1 < NW4) cv1 = cvs[k1];
    }

    if (GELU) {
        grid_dep_sync();      // wait for scatter completion
        grid_dep_trigger();   // let GEMM2 launch (it self-syncs via flags)
    } else {
        grid_dep_trigger();   // let combine launch (it self-syncs via flags)
    }

    int row0 = blockIdx.y * BM;
    if (row0 >= g_offs[E]) {
        if (CONV) {
            if (cbase + tid < NW4) cvd[cbase + tid] = f4_to_h4(cv0);
            if (cbase + NTHREADS + tid < NW4) cvd[cbase + NTHREADS + tid] = f4_to_h4(cv1);
#pragma unroll 4
            for (int j = 2; j < 32; j++) {
                int k = cbase + j * NTHREADS + tid;
                if (k < NW4) cvd[k] = f4_to_h4(cvs[k]);
            }
            __threadfence();
            __syncthreads();
            if (tid == 0 && cbase < NW4)
                atomicAdd(&g_conv[cbase >> SLAB_SHIFT], 1);
        }
        return;
    }
    int e = 0;
#pragma unroll
    for (int i = 1; i < E; i++) if (row0 >= g_offs[i]) e = i;
    int col0 = blockIdx.x * BN;
    const __half* Bexp = Ball + (size_t)e * KTOT * NLD + col0;

    if (!GELU) {
        // spin until h1 rowtile + w2h expert slab are fully produced
        if (tid == 0) {
            while (ld_acquire(&g_done1[blockIdx.y]) < 32) { }
            while (ld_acquire(&g_conv[e]) < 256) { }
        }
        __syncthreads();
    }

    extern __shared__ __align__(16) char dsm[];
    __shared__ int s_tok[BM];

    int wid = tid >> 5, lane = tid & 31;
    int wm = wid & 1, wn = wid >> 1;
    int g = lane >> 2, tg = lane & 3;
    int l15 = lane & 15, l16 = (lane >> 4) * 8;

    if (GATHER) s_tok[tid] = g_tok[row0 + tid];
    __syncthreads();

    uint32_t sAb = smem_u32(dsm);
    uint32_t sBb = sAb + PIPE * ASZ;

    const __half* a_gptr[8];
#pragma unroll
    for (int i = 0; i < 8; i++) {
        int idx = tid + i * NTHREADS;
        int r = idx >> 3, c = idx & 7;
        int rowid = GATHER ? s_tok[r] : (row0 + r);
        a_gptr[i] = Aall + (size_t)rowid * KTOT + c * 8;
    }
    const __half* b_gptr[8];
#pragma unroll
    for (int i = 0; i < 8; i++) {
        int idx = tid + i * NTHREADS;
        b_gptr[i] = Bexp + (size_t)(idx >> 4) * NLD + (idx & 15) * 8;
    }

    auto issue_copy = [&](int chunk, int buf) {
        uint32_t sa = sAb + buf * ASZ;
        uint32_t sb = sBb + buf * BSZ;
        int k0 = chunk * BK;
#pragma unroll
        for (int i = 0; i < 8; i++) {
            int idx = tid + i * NTHREADS;
            int r = idx >> 3, c = idx & 7;
            cp_async16(sa + (uint32_t)(r * ASTR + c * 8) * 2, a_gptr[i] + k0);
        }
#pragma unroll
        for (int i = 0; i < 8; i++) {
            int idx = tid + i * NTHREADS;
            int r = idx >> 4, c = idx & 15;
            cp_async16(sb + (uint32_t)(r * BSTR + c * 8) * 2,
                       b_gptr[i] + (size_t)k0 * NLD);
        }
        asm volatile("cp.async.commit_group;" ::: "memory");
    };

    float acc[4][8][4];
#pragma unroll
    for (int mf = 0; mf < 4; mf++)
#pragma unroll
        for (int nf = 0; nf < 8; nf++)
#pragma unroll
            for (int r = 0; r < 4; r++) acc[mf][nf][r] = 0.f;

    const int NC = KTOT / BK;   // 16 (gemm1) / 64 (gemm2)

    issue_copy(0, 0);
    issue_copy(1, 1);

    int buf = 0;
    for (int i = 0; i < NC; i++) {
        if (i + 1 < NC) asm volatile("cp.async.wait_group 1;" ::: "memory");
        else            asm volatile("cp.async.wait_group 0;" ::: "memory");
        __syncthreads();

        if (CONV) {
            int k0 = cbase + i * 2 * NTHREADS + tid;
            int k1 = k0 + NTHREADS;
            if (k0 < NW4) cvd[k0] = f4_to_h4(cv0);
            if (k1 < NW4) cvd[k1] = f4_to_h4(cv1);
            if (i + 1 < NC) {
                int n0 = k0 + 2 * NTHREADS, n1 = k1 + 2 * NTHREADS;
                if (n0 < NW4) cv0 = cvs[n0];
                if (n1 < NW4) cv1 = cvs[n1];
            }
        }

        if (i + 2 < NC) {
            int nb = buf + 2; if (nb >= PIPE) nb -= PIPE;
            issue_copy(i + 2, nb);
        }

        uint32_t sa = sAb + buf * ASZ;
        uint32_t sb = sBb + buf * BSZ;

#pragma unroll
        for (int kk = 0; kk < BK / 16; kk++) {
            uint32_t af[4][4];
#pragma unroll
            for (int mf = 0; mf < 4; mf++) {
                uint32_t addr = sa + (uint32_t)((wm * 64 + mf * 16 + l15) * ASTR
                                                + kk * 16 + l16) * 2;
                LDSM_X4(af[mf][0], af[mf][1], af[mf][2], af[mf][3], addr);
            }
            uint32_t bf[8][2];
#pragma unroll
            for (int pf = 0; pf < 4; pf++) {
                uint32_t addr = sb + (uint32_t)((kk * 16 + l15) * BSTR
                                                + wn * 64 + pf * 16 + l16) * 2;
                uint32_t r0, r1, r2, r3;
                LDSM_X4T(r0, r1, r2, r3, addr);
                bf[pf * 2][0] = r0;     bf[pf * 2][1] = r1;
                bf[pf * 2 + 1][0] = r2; bf[pf * 2 + 1][1] = r3;
            }
#pragma unroll
            for (int mf = 0; mf < 4; mf++)
#pragma unroll
                for (int nf = 0; nf < 8; nf++)
                    mma_f16(acc[mf][nf], af[mf], bf[nf]);
        }
        buf++; if (buf >= PIPE) buf -= PIPE;
    }

    // epilogue
    const float* be = bias + (size_t)e * NLD + col0 + wn * 64;
#pragma unroll
    for (int mf = 0; mf < 4; mf++) {
        int r0 = row0 + wm * 64 + mf * 16 + g;
#pragma unroll
        for (int nf = 0; nf < 8; nf++) {
            int cl = nf * 8 + tg * 2;
            float b0 = be[cl], b1 = be[cl + 1];
            float v0 = acc[mf][nf][0] + b0;
            float v1 = acc[mf][nf][1] + b1;
            float v2 = acc[mf][nf][2] + b0;
            float v3 = acc[mf][nf][3] + b1;
            int c = col0 + wn * 64 + cl;
            if (GELU) {
                const float kk = 0.70710678118654752440f;
                v0 = 0.5f * v0 * (1.f + erff(v0 * kk));
                v1 = 0.5f * v1 * (1.f + erff(v1 * kk));
                v2 = 0.5f * v2 * (1.f + erff(v2 * kk));
                v3 = 0.5f * v3 * (1.f + erff(v3 * kk));
                __half2 h01 = __float22half2_rn(make_float2(v0, v1));
                __half2 h23 = __float22half2_rn(make_float2(v2, v3));
                *(__half2*)(g_h1 + (size_t)r0 * NLD + c)       = h01;
                *(__half2*)(g_h1 + (size_t)(r0 + 8) * NLD + c) = h23;
            } else {
                *(float2*)(g_y + (size_t)r0 * NLD + c)       = make_float2(v0, v1);
                *(float2*)(g_y + (size_t)(r0 + 8) * NLD + c) = make_float2(v2, v3);
            }
        }
    }

    // publish readiness
    __threadfence();
    __syncthreads();
    if (tid == 0) {
        if (GELU) {
            atomicAdd(&g_done1[blockIdx.y], 1);
            if (CONV && cbase < NW4) atomicAdd(&g_conv[cbase >> SLAB_SHIFT], 1);
        } else {
            atomicAdd(&g_done2[blockIdx.y], 1);
        }
    }
}

// ---------------- combine (spin on g_done2; +counter re-zero) ----------------
__global__ void __launch_bounds__(256)
combine_kernel(const float* __restrict__ x,
               const float* __restrict__ gamma,
               const float* __restrict__ beta,
               float* __restrict__ out) {
    int t = blockIdx.x;
    int tid = threadIdx.x;

    if (blockIdx.x == 0 && tid < E) { g_count[tid] = 0; g_fill[tid] = 0; }

    int s0 = g_slot[t * 2 + 0], s1 = g_slot[t * 2 + 1];
    int e0 = g_texp[t * 2 + 0], e1 = g_texp[t * 2 + 1];
    float p0 = g_tprob[t * 2 + 0], p1 = g_tprob[t * 2 + 1];

    // wait for GEMM2 rowtiles covering both slots
    if (tid == 0) {
        while (ld_acquire(&g_done2[s0 >> 7]) < 8) { }
        while (ld_acquire(&g_done2[s1 >> 7]) < 8) { }
    }
    __syncthreads();

    const float* y0 = g_y + (size_t)s0 * D;
    const float* y1 = g_y + (size_t)s1 * D;
    const float* xt = x + (size_t)t * D;

    float v0[4], v1[4];
    float sum0 = 0.f, sq0 = 0.f, sum1 = 0.f, sq1 = 0.f;
#pragma unroll
    for (int i = 0; i < 4; i++) {
        int d = tid + i * 256;
        float xv = xt[d];
        v0[i] = y0[d] + xv;
        v1[i] = y1[d] + xv;
        sum0 += v0[i]; sq0 += v0[i] * v0[i];
        sum1 += v1[i]; sq1 += v1[i] * v1[i];
    }

    __shared__ float sh[4][8];
    int lane = tid & 31, wid = tid >> 5;
#pragma unroll
    for (int off = 16; off > 0; off >>= 1) {
        sum0 += __shfl_down_sync(0xffffffffu, sum0, off);
        sq0  += __shfl_down_sync(0xffffffffu, sq0,  off);
        sum1 += __shfl_down_sync(0xffffffffu, sum1, off);
        sq1  += __shfl_down_sync(0xffffffffu, sq1,  off);
    }
    if (lane == 0) {
        sh[0][wid] = sum0; sh[1][wid] = sq0;
        sh[2][wid] = sum1; sh[3][wid] = sq1;
    }
    __syncthreads();
    __shared__ float fin[4];
    if (wid == 0) {
        float a = (lane < 8) ? sh[0][lane] : 0.f;
        float b = (lane < 8) ? sh[1][lane] : 0.f;
        float c = (lane < 8) ? sh[2][lane] : 0.f;
        float d = (lane < 8) ? sh[3][lane] : 0.f;
#pragma unroll
        for (int off = 4; off > 0; off >>= 1) {
            a += __shfl_down_sync(0xffffffffu, a, off);
            b += __shfl_down_sync(0xffffffffu, b, off);
            c += __shfl_down_sync(0xffffffffu, c, off);
            d += __shfl_down_sync(0xffffffffu, d, off);
        }
        if (lane == 0) { fin[0] = a; fin[1] = b; fin[2] = c; fin[3] = d; }
    }
    __syncthreads();

    float mu0 = fin[0] * (1.f / D);
    float var0 = fin[1] * (1.f / D) - mu0 * mu0;
    float rs0 = rsqrtf(var0 + 1e-5f);
    float mu1 = fin[2] * (1.f / D);
    float var1 = fin[3] * (1.f / D) - mu1 * mu1;
    float rs1 = rsqrtf(var1 + 1e-5f);

    const float* g0 = gamma + (size_t)e0 * D;
    const float* b0 = beta  + (size_t)e0 * D;
    const float* g1 = gamma + (size_t)e1 * D;
    const float* b1v = beta + (size_t)e1 * D;

#pragma unroll
    for (int i = 0; i < 4; i++) {
        int d = tid + i * 256;
        float o0 = (v0[i] - mu0) * rs0 * g0[d] + b0[d];
        float o1 = (v1[i] - mu1) * rs1 * g1[d] + b1v[d];
        out[(size_t)t * D + d] = p0 * o0 + p1 * o1;
    }
    grid_dep_trigger();
}

// ---------------- launch helper with PDL attribute ----------------
template<typename... Args>
static void launch_pdl(void (*kern)(Args...), dim3 grid, dim3 block,
                       size_t smem, cudaStream_t stream, Args... args) {
    cudaLaunchAttribute attr[1];
    attr[0].id = cudaLaunchAttributeProgrammaticStreamSerialization;
    attr[0].val.programmaticStreamSerializationAllowed = 1;
    cudaLaunchConfig_t cfg = {};
    cfg.gridDim = grid;
    cfg.blockDim = block;
    cfg.dynamicSmemBytes = smem;
    cfg.stream = stream;
    cfg.attrs = attr;
    cfg.numAttrs = 1;
    cudaLaunchKernelEx(&cfg, kern, args...);
}

// ---------------- launch ----------------
extern "C" void kernel_launch(void* const* d_in, const int* in_sizes, int n_in,
                              void* d_out, int out_size) {
    const float* x        = (const float*)d_in[0];
    const float* router_w = (const float*)d_in[1];
    const float* router_b = (const float*)d_in[2];
    const float* w1       = (const float*)d_in[3];
    const float* b1       = (const float*)d_in[4];
    const float* w2       = (const float*)d_in[5];
    const float* b2       = (const float*)d_in[6];
    const float* gamma    = (const float*)d_in[7];
    const float* beta     = (const float*)d_in[8];

    float* out = (float*)d_out;
    float* out_logits = out + (size_t)T * D;

    static int configured = 0;
    if (!configured) {
        cudaFuncSetAttribute(moe_gemm<D, H, true, true, true>,
                             cudaFuncAttributeMaxDynamicSharedMemorySize, SMEM_DYN);
        cudaFuncSetAttribute(moe_gemm<H, D, false, false, false>,
                             cudaFuncAttributeMaxDynamicSharedMemorySize, SMEM_DYN);
        configured = 1;
    }

    __half* d_w1h; cudaGetSymbolAddress((void**)&d_w1h, g_w1h);
    __half* d_w2h; cudaGetSymbolAddress((void**)&d_w2h, g_w2h);

    cudaStream_t s = 0;

    int conv_blocks = (NW4 + 255) / 256;
    launch_pdl(fused_prep_kernel,
               dim3(NROUTER_BLOCKS + conv_blocks), dim3(256), 0, s,
               x, router_w, router_b,
               (const float4*)w1, (uint2*)d_w1h, out_logits);

    launch_pdl(scatter_kernel, dim3(T / 256), dim3(256), 0, s);

    launch_pdl(moe_gemm<D, H, true, true, true>,
               dim3(H / BN, ROWTILES), dim3(NTHREADS), (size_t)SMEM_DYN, s,
               b1, (const float4*)w2, (uint2*)d_w2h);
    launch_pdl(moe_gemm<H, D, false, false, false>,
               dim3(D / BN, ROWTILES), dim3(NTHREADS), (size_t)SMEM_DYN, s,
               b2, (const float4*)nullptr, (uint2*)nullptr);

    launch_pdl(combine_kernel, dim3(T), dim3(256), 0, s,
               x, gamma, beta, out);
}